// round 6
// baseline (speedup 1.0000x reference)
#include <cuda_runtime.h>

#define PMAX 32
#define COUT 64
#define GRID 296
#define VPBMAX 160
#define EPSV 1e-5f

// Scratch (no allocations): per-block partials + barrier state.
__device__ float g_part[GRID * 16];
__device__ unsigned g_count = 0;     // arrive counter (returns to 0 each launch)
__device__ unsigned g_release = 0;   // monotonically increasing generation

typedef unsigned long long u64;

__device__ __forceinline__ u64 pk2(float a, float b) {
    u64 r; asm("mov.b64 %0, {%1,%2};" : "=l"(r) : "f"(a), "f"(b)); return r;
}
__device__ __forceinline__ void upk2(u64 v, float& a, float& b) {
    asm("mov.b64 {%0,%1}, %2;" : "=f"(a), "=f"(b) : "l"(v));
}
__device__ __forceinline__ u64 fma2(u64 a, u64 b, u64 c) {
    u64 d; asm("fma.rn.f32x2 %0, %1, %2, %3;" : "=l"(d) : "l"(a), "l"(b), "l"(c)); return d;
}

__global__ void __launch_bounds__(256, 2) fused_kernel(
    const float* __restrict__ feat, const int* __restrict__ npts,
    const float* __restrict__ W, const float* __restrict__ b,
    const float* __restrict__ gamma, const float* __restrict__ beta,
    float* __restrict__ out, int M, int vpb)
{
    __shared__ int sm_n[VPBMAX];
    __shared__ float red[16][16];
    __shared__ float fin[16];
    __shared__ __align__(16) float sp[8][16 * 12];

    int tid = threadIdx.x;
    int w = tid >> 5, l = tid & 31;
    int vb = blockIdx.x * vpb;

    for (int i = tid; i < vpb; i += 256)
        sm_n[i] = (vb + i < M) ? __ldg(&npts[vb + i]) : 0;
    __syncthreads();

    // ================= Phase A: masked stats over this block's slab =========
    float cnt = 0.f;
    float s0=0,s1=0,s2=0,s3=0;
    float q00=0,q01=0,q02=0,q03=0,q11=0,q12=0,q13=0,q22=0,q23=0,q33=0;

    const float4* fbase = ((const float4*)feat) + (size_t)vb * PMAX;
    int slots = vpb * PMAX;
    #pragma unroll 4
    for (int i = tid; i < slots; i += 256) {
        int m = i >> 5, p = i & 31;
        bool ok = (p < sm_n[m]);
        float4 v = make_float4(0.f, 0.f, 0.f, 0.f);
        if (ok) v = __ldg(&fbase[i]);
        if (ok) cnt += 1.f;
        s0 += v.x; s1 += v.y; s2 += v.z; s3 += v.w;
        q00 += v.x*v.x; q01 += v.x*v.y; q02 += v.x*v.z; q03 += v.x*v.w;
        q11 += v.y*v.y; q12 += v.y*v.z; q13 += v.y*v.w;
        q22 += v.z*v.z; q23 += v.z*v.w; q33 += v.w*v.w;
    }

    float vals[15] = {cnt, s0,s1,s2,s3, q00,q01,q02,q03,q11,q12,q13,q22,q23,q33};
    #pragma unroll
    for (int k = 0; k < 15; k++) {
        #pragma unroll
        for (int off = 16; off > 0; off >>= 1)
            vals[k] += __shfl_down_sync(0xffffffffu, vals[k], off);
    }
    if (l == 0) {
        #pragma unroll
        for (int k = 0; k < 15; k++) red[w][k] = vals[k];   // reuse red as [8][16]
    }
    __syncthreads();
    if (tid < 15) {
        float t = 0.f;
        #pragma unroll
        for (int ww = 0; ww < 8; ww++) t += red[ww][tid];
        g_part[blockIdx.x * 16 + tid] = t;
        __threadfence();
    }
    __syncthreads();

    // ================= Grid barrier (deterministic) =========================
    if (tid == 0) {
        unsigned old = *((volatile unsigned*)&g_release);
        unsigned a = atomicAdd(&g_count, 1);
        if (a == gridDim.x - 1) {
            g_count = 0;
            __threadfence();
            *((volatile unsigned*)&g_release) = old + 1;
        } else {
            while (*((volatile unsigned*)&g_release) == old) { }
            __threadfence();
        }
    }
    __syncthreads();

    // ================= Fold: every block reduces all partials ===============
    {
        int stat = tid & 15, grp = tid >> 4;
        float s = 0.f;
        for (int k = grp; k < (int)gridDim.x; k += 16)
            s += g_part[k * 16 + stat];
        red[grp][stat] = s;
    }
    __syncthreads();
    if (tid < 16) {
        float tt = 0.f;
        #pragma unroll
        for (int g = 0; g < 16; g++) tt += red[g][tid];
        fin[tid] = tt;
    }
    __syncthreads();

    // Per-thread BN fold for channels o0 = l and o1 = l + 32.
    float N  = fmaxf(fin[0], 1.f);
    float invN = 1.f / N;
    float S0 = fin[1], S1 = fin[2], S2 = fin[3], S3 = fin[4];
    float f00=fin[5], f01=fin[6], f02=fin[7], f03=fin[8];
    float f11=fin[9], f12=fin[10], f13=fin[11];
    float f22=fin[12], f23=fin[13], f33=fin[14];

    float wa0, wa1, wa2, wa3, ba, wb0, wb1, wb2, wb3, bb;
    #pragma unroll
    for (int half = 0; half < 2; half++) {
        int o = l + half * 32;
        float w0 = __ldg(&W[o*4+0]), w1 = __ldg(&W[o*4+1]);
        float w2 = __ldg(&W[o*4+2]), w3 = __ldg(&W[o*4+3]);
        float bo = __ldg(&b[o]);
        float wS = w0*S0 + w1*S1 + w2*S2 + w3*S3;
        float mu = (wS + bo * N) * invN;
        float wQw = w0*(f00*w0 + f01*w1 + f02*w2 + f03*w3)
                  + w1*(f01*w0 + f11*w1 + f12*w2 + f13*w3)
                  + w2*(f02*w0 + f12*w1 + f22*w2 + f23*w3)
                  + w3*(f03*w0 + f13*w1 + f23*w2 + f33*w3);
        float Eh2 = (wQw + 2.f*bo*wS + bo*bo*N) * invN;
        float var = fmaxf(Eh2 - mu*mu, 0.f);
        float sc  = __ldg(&gamma[o]) * rsqrtf(var + EPSV);
        float bf  = sc * (bo - mu) + __ldg(&beta[o]);
        if (half == 0) { wa0=sc*w0; wa1=sc*w1; wa2=sc*w2; wa3=sc*w3; ba=bf; }
        else           { wb0=sc*w0; wb1=sc*w1; wb2=sc*w2; wb3=sc*w3; bb=bf; }
    }

    u64 WA0 = pk2(wa0, wa0), WA1 = pk2(wa1, wa1), WA2 = pk2(wa2, wa2), WA3 = pk2(wa3, wa3);
    u64 WB0 = pk2(wb0, wb0), WB1 = pk2(wb1, wb1), WB2 = pk2(wb2, wb2), WB3 = pk2(wb3, wb3);
    u64 BA  = pk2(ba, ba),   BB  = pk2(bb, bb);
    u64 H2  = pk2(0.5f, 0.5f);
    const u64 ABSM = 0x7FFFFFFF7FFFFFFFULL;

    // ================= Phase B: warp-per-voxel GEMV over the slab ===========
    float* s = sp[w];
    for (int mv = w; mv < vpb; mv += 8) {
        int m = vb + mv;
        if (m >= M) break;           // warp-uniform
        int n = sm_n[mv];

        __syncwarp();                // previous iteration's reads done
        if (l < n) {
            float4 v = __ldg(&((const float4*)feat)[(size_t)m * PMAX + l]);
            int base = (l >> 1) * 12 + (l & 1);
            s[base + 0] = v.x;
            s[base + 2] = v.y;
            s[base + 4] = v.z;
            s[base + 6] = v.w;
        }
        __syncwarp();

        u64 ACCA = 0ULL, ACCB = 0ULL;
        int pairs = n >> 1;
        #pragma unroll 4
        for (int j = 0; j < pairs; j++) {
            const ulonglong2* q = reinterpret_cast<const ulonglong2*>(s + j * 12);
            ulonglong2 q0 = q[0];
            ulonglong2 q1 = q[1];
            u64 hA = BA, hB = BB;
            hA = fma2(WA0, q0.x, hA); hA = fma2(WA1, q0.y, hA);
            hA = fma2(WA2, q1.x, hA); hA = fma2(WA3, q1.y, hA);
            hB = fma2(WB0, q0.x, hB); hB = fma2(WB1, q0.y, hB);
            hB = fma2(WB2, q1.x, hB); hB = fma2(WB3, q1.y, hB);
            u64 aA = hA & ABSM;
            u64 aB = hB & ABSM;
            ACCA = fma2(H2, hA, ACCA);
            ACCA = fma2(H2, aA, ACCA);
            ACCB = fma2(H2, hB, ACCB);
            ACCB = fma2(H2, aB, ACCB);
        }

        float r0, r1;
        upk2(ACCA, r0, r1); float acc0 = r0 + r1;
        upk2(ACCB, r0, r1); float acc1 = r0 + r1;

        if (n & 1) {
            int p = n - 1;
            const float* sb = s + (p >> 1) * 12;
            float x0 = sb[0], x1 = sb[2], x2 = sb[4], x3 = sb[6];
            float hA = fmaf(wa0, x0, fmaf(wa1, x1, fmaf(wa2, x2, fmaf(wa3, x3, ba))));
            float hB = fmaf(wb0, x0, fmaf(wb1, x1, fmaf(wb2, x2, fmaf(wb3, x3, bb))));
            acc0 += fmaxf(hA, 0.f);
            acc1 += fmaxf(hB, 0.f);
        }

        float inv = 1.f / fmaxf((float)n, 1.f);
        out[(size_t)m * COUT + l]      = acc0 * inv;
        out[(size_t)m * COUT + 32 + l] = acc1 * inv;
    }
}

// ---------------------------------------------------------------------------
extern "C" void kernel_launch(void* const* d_in, const int* in_sizes, int n_in,
                              void* d_out, int out_size)
{
    const float* feat  = (const float*)d_in[0];
    const int*   npts  = (const int*)d_in[1];
    const float* W     = (const float*)d_in[2];
    const float* b     = (const float*)d_in[3];
    const float* gamma = (const float*)d_in[4];
    const float* beta  = (const float*)d_in[5];
    float* out = (float*)d_out;
    int M = in_sizes[1];

    int vpb = (M + GRID - 1) / GRID;        // 136 for M=40000
    if (vpb > VPBMAX) vpb = VPBMAX;          // (problem shape is fixed; stays in range)

    fused_kernel<<<GRID, 256>>>(feat, npts, W, b, gamma, beta, out, M, vpb);
}

// round 7
// speedup vs baseline: 1.5152x; 1.5152x over previous
#include <cuda_runtime.h>

#define PMAX 32
#define COUT 64
#define GRID 296
#define NTHR 512
#define NWARP 16
#define VPBMAX 160
#define EPSV 1e-5f

// Scratch (no allocations): per-block partials + barrier state.
__device__ float g_part[GRID * 16];
__device__ unsigned g_count = 0;     // arrive counter (returns to 0 each launch)
__device__ unsigned g_release = 0;   // monotonically increasing generation

typedef unsigned long long u64;

__device__ __forceinline__ u64 pk2(float a, float b) {
    u64 r; asm("mov.b64 %0, {%1,%2};" : "=l"(r) : "f"(a), "f"(b)); return r;
}
__device__ __forceinline__ void upk2(u64 v, float& a, float& b) {
    asm("mov.b64 {%0,%1}, %2;" : "=f"(a), "=f"(b) : "l"(v));
}
__device__ __forceinline__ u64 fma2(u64 a, u64 b, u64 c) {
    u64 d; asm("fma.rn.f32x2 %0, %1, %2, %3;" : "=l"(d) : "l"(a), "l"(b), "l"(c)); return d;
}

__global__ void __launch_bounds__(NTHR, 2) fused_kernel(
    const float* __restrict__ feat, const int* __restrict__ npts,
    const float* __restrict__ W, const float* __restrict__ b,
    const float* __restrict__ gamma, const float* __restrict__ beta,
    float* __restrict__ out, int M, int vpb)
{
    __shared__ int sm_n[VPBMAX];
    __shared__ float red[32][16];
    __shared__ float fin[16];
    __shared__ __align__(16) float sp[NWARP][16 * 12];

    int tid = threadIdx.x;
    int w = tid >> 5, l = tid & 31;
    int vb = blockIdx.x * vpb;

    for (int i = tid; i < vpb; i += NTHR)
        sm_n[i] = (vb + i < M) ? __ldg(&npts[vb + i]) : 0;
    __syncthreads();

    // ================= Phase A: masked stats over this block's slab =========
    float cnt = 0.f;
    float s0=0,s1=0,s2=0,s3=0;
    float q00=0,q01=0,q02=0,q03=0,q11=0,q12=0,q13=0,q22=0,q23=0,q33=0;

    const float4* fbase = ((const float4*)feat) + (size_t)vb * PMAX;
    int slots = vpb * PMAX;
    #pragma unroll 4
    for (int i = tid; i < slots; i += NTHR) {
        int m = i >> 5, p = i & 31;
        bool ok = (p < sm_n[m]);
        float4 v = make_float4(0.f, 0.f, 0.f, 0.f);
        if (ok) v = __ldg(&fbase[i]);
        if (ok) cnt += 1.f;
        s0 += v.x; s1 += v.y; s2 += v.z; s3 += v.w;
        q00 += v.x*v.x; q01 += v.x*v.y; q02 += v.x*v.z; q03 += v.x*v.w;
        q11 += v.y*v.y; q12 += v.y*v.z; q13 += v.y*v.w;
        q22 += v.z*v.z; q23 += v.z*v.w; q33 += v.w*v.w;
    }

    float vals[15] = {cnt, s0,s1,s2,s3, q00,q01,q02,q03,q11,q12,q13,q22,q23,q33};
    #pragma unroll
    for (int k = 0; k < 15; k++) {
        #pragma unroll
        for (int off = 16; off > 0; off >>= 1)
            vals[k] += __shfl_down_sync(0xffffffffu, vals[k], off);
    }
    if (l == 0) {
        #pragma unroll
        for (int k = 0; k < 15; k++) red[w][k] = vals[k];   // red rows 0..15 used
    }
    __syncthreads();
    if (tid < 15) {
        float t = 0.f;
        #pragma unroll
        for (int ww = 0; ww < NWARP; ww++) t += red[ww][tid];
        g_part[blockIdx.x * 16 + tid] = t;
        __threadfence();
    }
    __syncthreads();

    // ================= Grid barrier (deterministic) =========================
    if (tid == 0) {
        unsigned old = *((volatile unsigned*)&g_release);
        unsigned a = atomicAdd(&g_count, 1);
        if (a == gridDim.x - 1) {
            g_count = 0;
            __threadfence();
            *((volatile unsigned*)&g_release) = old + 1;
        } else {
            while (*((volatile unsigned*)&g_release) == old) { }
            __threadfence();
        }
    }
    __syncthreads();

    // ================= Fold: every block reduces all partials ===============
    {
        int stat = tid & 15, grp = tid >> 4;     // 32 groups of 16 stats
        float s = 0.f;
        for (int k = grp; k < (int)gridDim.x; k += 32)
            s += g_part[k * 16 + stat];
        red[grp][stat] = s;
    }
    __syncthreads();
    if (tid < 16) {
        float tt = 0.f;
        #pragma unroll
        for (int g = 0; g < 32; g++) tt += red[g][tid];
        fin[tid] = tt;
    }
    __syncthreads();

    // Per-thread BN fold for channels o0 = l and o1 = l + 32.
    float N  = fmaxf(fin[0], 1.f);
    float invN = 1.f / N;
    float S0 = fin[1], S1 = fin[2], S2 = fin[3], S3 = fin[4];
    float f00=fin[5], f01=fin[6], f02=fin[7], f03=fin[8];
    float f11=fin[9], f12=fin[10], f13=fin[11];
    float f22=fin[12], f23=fin[13], f33=fin[14];

    float wa0, wa1, wa2, wa3, ba, wb0, wb1, wb2, wb3, bb;
    #pragma unroll
    for (int half = 0; half < 2; half++) {
        int o = l + half * 32;
        float w0 = __ldg(&W[o*4+0]), w1 = __ldg(&W[o*4+1]);
        float w2 = __ldg(&W[o*4+2]), w3 = __ldg(&W[o*4+3]);
        float bo = __ldg(&b[o]);
        float wS = w0*S0 + w1*S1 + w2*S2 + w3*S3;
        float mu = (wS + bo * N) * invN;
        float wQw = w0*(f00*w0 + f01*w1 + f02*w2 + f03*w3)
                  + w1*(f01*w0 + f11*w1 + f12*w2 + f13*w3)
                  + w2*(f02*w0 + f12*w1 + f22*w2 + f23*w3)
                  + w3*(f03*w0 + f13*w1 + f23*w2 + f33*w3);
        float Eh2 = (wQw + 2.f*bo*wS + bo*bo*N) * invN;
        float var = fmaxf(Eh2 - mu*mu, 0.f);
        float sc  = __ldg(&gamma[o]) * rsqrtf(var + EPSV);
        float bf  = sc * (bo - mu) + __ldg(&beta[o]);
        if (half == 0) { wa0=sc*w0; wa1=sc*w1; wa2=sc*w2; wa3=sc*w3; ba=bf; }
        else           { wb0=sc*w0; wb1=sc*w1; wb2=sc*w2; wb3=sc*w3; bb=bf; }
    }

    u64 WA0 = pk2(wa0, wa0), WA1 = pk2(wa1, wa1), WA2 = pk2(wa2, wa2), WA3 = pk2(wa3, wa3);
    u64 WB0 = pk2(wb0, wb0), WB1 = pk2(wb1, wb1), WB2 = pk2(wb2, wb2), WB3 = pk2(wb3, wb3);
    u64 BA  = pk2(ba, ba),   BB  = pk2(bb, bb);
    u64 H2  = pk2(0.5f, 0.5f);
    const u64 ABSM = 0x7FFFFFFF7FFFFFFFULL;

    // ================= Phase B: warp-per-voxel GEMV over the slab ===========
    float* s = sp[w];
    for (int mv = w; mv < vpb; mv += NWARP) {
        int m = vb + mv;
        if (m >= M) break;           // warp-uniform
        int n = sm_n[mv];

        __syncwarp();                // previous iteration's reads done
        if (l < n) {
            float4 v = __ldg(&((const float4*)feat)[(size_t)m * PMAX + l]);
            int base = (l >> 1) * 12 + (l & 1);
            s[base + 0] = v.x;
            s[base + 2] = v.y;
            s[base + 4] = v.z;
            s[base + 6] = v.w;
        }
        __syncwarp();

        u64 ACCA = 0ULL, ACCB = 0ULL;
        int pairs = n >> 1;
        #pragma unroll 4
        for (int j = 0; j < pairs; j++) {
            const ulonglong2* q = reinterpret_cast<const ulonglong2*>(s + j * 12);
            ulonglong2 q0 = q[0];
            ulonglong2 q1 = q[1];
            u64 hA = BA, hB = BB;
            hA = fma2(WA0, q0.x, hA); hA = fma2(WA1, q0.y, hA);
            hA = fma2(WA2, q1.x, hA); hA = fma2(WA3, q1.y, hA);
            hB = fma2(WB0, q0.x, hB); hB = fma2(WB1, q0.y, hB);
            hB = fma2(WB2, q1.x, hB); hB = fma2(WB3, q1.y, hB);
            u64 aA = hA & ABSM;
            u64 aB = hB & ABSM;
            ACCA = fma2(H2, hA, ACCA);
            ACCA = fma2(H2, aA, ACCA);
            ACCB = fma2(H2, hB, ACCB);
            ACCB = fma2(H2, aB, ACCB);
        }

        float r0, r1;
        upk2(ACCA, r0, r1); float acc0 = r0 + r1;
        upk2(ACCB, r0, r1); float acc1 = r0 + r1;

        if (n & 1) {
            int p = n - 1;
            const float* sb = s + (p >> 1) * 12;
            float x0 = sb[0], x1 = sb[2], x2 = sb[4], x3 = sb[6];
            float hA = fmaf(wa0, x0, fmaf(wa1, x1, fmaf(wa2, x2, fmaf(wa3, x3, ba))));
            float hB = fmaf(wb0, x0, fmaf(wb1, x1, fmaf(wb2, x2, fmaf(wb3, x3, bb))));
            acc0 += fmaxf(hA, 0.f);
            acc1 += fmaxf(hB, 0.f);
        }

        float inv = 1.f / fmaxf((float)n, 1.f);
        out[(size_t)m * COUT + l]      = acc0 * inv;
        out[(size_t)m * COUT + 32 + l] = acc1 * inv;
    }
}

// ---------------------------------------------------------------------------
extern "C" void kernel_launch(void* const* d_in, const int* in_sizes, int n_in,
                              void* d_out, int out_size)
{
    const float* feat  = (const float*)d_in[0];
    const int*   npts  = (const int*)d_in[1];
    const float* W     = (const float*)d_in[2];
    const float* b     = (const float*)d_in[3];
    const float* gamma = (const float*)d_in[4];
    const float* beta  = (const float*)d_in[5];
    float* out = (float*)d_out;
    int M = in_sizes[1];

    int vpb = (M + GRID - 1) / GRID;        // 136 for M=40000
    if (vpb > VPBMAX) vpb = VPBMAX;          // (problem shape fixed; stays in range)

    fused_kernel<<<GRID, NTHR>>>(feat, npts, W, b, gamma, beta, out, M, vpb);
}

// round 8
// speedup vs baseline: 1.5552x; 1.0264x over previous
#include <cuda_runtime.h>

#define PMAX 32
#define COUT 64
#define GRID 296
#define NTHR 512
#define NWARP 16
#define VPBMAX 160
#define SLABW 192          // floats per voxel in smem slab (16 pairs * 12 words)
#define EPSV 1e-5f

// Scratch (no allocations): per-block partials + barrier state.
__device__ float g_part[GRID * 16];
__device__ unsigned g_count = 0;     // arrive counter (returns to 0 each launch)
__device__ unsigned g_release = 0;   // monotonically increasing generation

typedef unsigned long long u64;

__device__ __forceinline__ u64 pk2(float a, float b) {
    u64 r; asm("mov.b64 %0, {%1,%2};" : "=l"(r) : "f"(a), "f"(b)); return r;
}
__device__ __forceinline__ void upk2(u64 v, float& a, float& b) {
    asm("mov.b64 {%0,%1}, %2;" : "=f"(a), "=f"(b) : "l"(v));
}
__device__ __forceinline__ u64 fma2(u64 a, u64 b, u64 c) {
    u64 d; asm("fma.rn.f32x2 %0, %1, %2, %3;" : "=l"(d) : "l"(a), "l"(b), "l"(c)); return d;
}

extern __shared__ float sm_slab[];   // vpb * SLABW floats (dynamic, ~104 KB)

__global__ void __launch_bounds__(NTHR, 2) fused_kernel(
    const float* __restrict__ feat, const int* __restrict__ npts,
    const float* __restrict__ W, const float* __restrict__ b,
    const float* __restrict__ gamma, const float* __restrict__ beta,
    float* __restrict__ out, int M, int vpb)
{
    __shared__ int sm_n[VPBMAX];
    __shared__ float red[32][16];
    __shared__ float fin[16];

    int tid = threadIdx.x;
    int w = tid >> 5, l = tid & 31;
    int vb = blockIdx.x * vpb;

    for (int i = tid; i < vpb; i += NTHR)
        sm_n[i] = (vb + i < M) ? __ldg(&npts[vb + i]) : 0;
    __syncthreads();

    // ===== Phase A: load feat ONCE -> stats + stage pair-transposed slab ====
    float cnt = 0.f;
    float s0=0,s1=0,s2=0,s3=0;
    float q00=0,q01=0,q02=0,q03=0,q11=0,q12=0,q13=0,q22=0,q23=0,q33=0;

    const float4* fbase = ((const float4*)feat) + (size_t)vb * PMAX;
    int slots = vpb * PMAX;
    #pragma unroll 4
    for (int i = tid; i < slots; i += NTHR) {
        int m = i >> 5, p = i & 31;
        bool ok = (p < sm_n[m]);
        float4 v = make_float4(0.f, 0.f, 0.f, 0.f);
        if (ok) v = __ldg(&fbase[i]);
        if (ok) {
            cnt += 1.f;
            float* d = sm_slab + m * SLABW + (p >> 1) * 12 + (p & 1);
            d[0] = v.x; d[2] = v.y; d[4] = v.z; d[6] = v.w;
        }
        s0 += v.x; s1 += v.y; s2 += v.z; s3 += v.w;
        q00 += v.x*v.x; q01 += v.x*v.y; q02 += v.x*v.z; q03 += v.x*v.w;
        q11 += v.y*v.y; q12 += v.y*v.z; q13 += v.y*v.w;
        q22 += v.z*v.z; q23 += v.z*v.w; q33 += v.w*v.w;
    }

    float vals[15] = {cnt, s0,s1,s2,s3, q00,q01,q02,q03,q11,q12,q13,q22,q23,q33};
    #pragma unroll
    for (int k = 0; k < 15; k++) {
        #pragma unroll
        for (int off = 16; off > 0; off >>= 1)
            vals[k] += __shfl_down_sync(0xffffffffu, vals[k], off);
    }
    if (l == 0) {
        #pragma unroll
        for (int k = 0; k < 15; k++) red[w][k] = vals[k];
    }
    __syncthreads();
    if (tid < 15) {
        float t = 0.f;
        #pragma unroll
        for (int ww = 0; ww < NWARP; ww++) t += red[ww][tid];
        g_part[blockIdx.x * 16 + tid] = t;
        __threadfence();
    }
    __syncthreads();

    // ================= Grid barrier (deterministic) =========================
    if (tid == 0) {
        unsigned old = *((volatile unsigned*)&g_release);
        unsigned a = atomicAdd(&g_count, 1);
        if (a == gridDim.x - 1) {
            g_count = 0;
            __threadfence();
            *((volatile unsigned*)&g_release) = old + 1;
        } else {
            while (*((volatile unsigned*)&g_release) == old) { }
            __threadfence();
        }
    }
    __syncthreads();

    // ================= Fold: every block reduces all partials ===============
    {
        int stat = tid & 15, grp = tid >> 4;     // 32 groups of 16 stats
        float s = 0.f;
        for (int k = grp; k < (int)gridDim.x; k += 32)
            s += g_part[k * 16 + stat];
        red[grp][stat] = s;
    }
    __syncthreads();
    if (tid < 16) {
        float tt = 0.f;
        #pragma unroll
        for (int g = 0; g < 32; g++) tt += red[g][tid];
        fin[tid] = tt;
    }
    __syncthreads();

    // Per-thread BN fold for channels o0 = l and o1 = l + 32.
    float N  = fmaxf(fin[0], 1.f);
    float invN = 1.f / N;
    float S0 = fin[1], S1 = fin[2], S2 = fin[3], S3 = fin[4];
    float f00=fin[5], f01=fin[6], f02=fin[7], f03=fin[8];
    float f11=fin[9], f12=fin[10], f13=fin[11];
    float f22=fin[12], f23=fin[13], f33=fin[14];

    float wa0, wa1, wa2, wa3, ba, wb0, wb1, wb2, wb3, bb;
    #pragma unroll
    for (int half = 0; half < 2; half++) {
        int o = l + half * 32;
        float w0 = __ldg(&W[o*4+0]), w1 = __ldg(&W[o*4+1]);
        float w2 = __ldg(&W[o*4+2]), w3 = __ldg(&W[o*4+3]);
        float bo = __ldg(&b[o]);
        float wS = w0*S0 + w1*S1 + w2*S2 + w3*S3;
        float mu = (wS + bo * N) * invN;
        float wQw = w0*(f00*w0 + f01*w1 + f02*w2 + f03*w3)
                  + w1*(f01*w0 + f11*w1 + f12*w2 + f13*w3)
                  + w2*(f02*w0 + f12*w1 + f22*w2 + f23*w3)
                  + w3*(f03*w0 + f13*w1 + f23*w2 + f33*w3);
        float Eh2 = (wQw + 2.f*bo*wS + bo*bo*N) * invN;
        float var = fmaxf(Eh2 - mu*mu, 0.f);
        float sc  = __ldg(&gamma[o]) * rsqrtf(var + EPSV);
        float bf  = sc * (bo - mu) + __ldg(&beta[o]);
        if (half == 0) { wa0=sc*w0; wa1=sc*w1; wa2=sc*w2; wa3=sc*w3; ba=bf; }
        else           { wb0=sc*w0; wb1=sc*w1; wb2=sc*w2; wb3=sc*w3; bb=bf; }
    }

    u64 WA0 = pk2(wa0, wa0), WA1 = pk2(wa1, wa1), WA2 = pk2(wa2, wa2), WA3 = pk2(wa3, wa3);
    u64 WB0 = pk2(wb0, wb0), WB1 = pk2(wb1, wb1), WB2 = pk2(wb2, wb2), WB3 = pk2(wb3, wb3);
    u64 BA  = pk2(ba, ba),   BB  = pk2(bb, bb);
    u64 H2  = pk2(0.5f, 0.5f);
    const u64 ABSM = 0x7FFFFFFF7FFFFFFFULL;

    // ===== Phase B: warp-per-voxel GEMV straight out of the smem slab =======
    for (int mv = w; mv < vpb; mv += NWARP) {
        int m = vb + mv;
        if (m >= M) break;           // warp-uniform
        int n = sm_n[mv];
        const float* s = sm_slab + mv * SLABW;

        u64 ACCA = 0ULL, ACCB = 0ULL;
        int pairs = n >> 1;
        #pragma unroll 4
        for (int j = 0; j < pairs; j++) {
            const ulonglong2* q = reinterpret_cast<const ulonglong2*>(s + j * 12);
            ulonglong2 q0 = q[0];    // packed (even,odd) for c=0, c=1
            ulonglong2 q1 = q[1];    // packed (even,odd) for c=2, c=3
            u64 hA = BA, hB = BB;
            hA = fma2(WA0, q0.x, hA); hA = fma2(WA1, q0.y, hA);
            hA = fma2(WA2, q1.x, hA); hA = fma2(WA3, q1.y, hA);
            hB = fma2(WB0, q0.x, hB); hB = fma2(WB1, q0.y, hB);
            hB = fma2(WB2, q1.x, hB); hB = fma2(WB3, q1.y, hB);
            u64 aA = hA & ABSM;      // |h| packed, ALU pipe
            u64 aB = hB & ABSM;
            ACCA = fma2(H2, hA, ACCA);   // += 0.5*h
            ACCA = fma2(H2, aA, ACCA);   // += 0.5*|h|  => += relu(h)
            ACCB = fma2(H2, hB, ACCB);
            ACCB = fma2(H2, aB, ACCB);
        }

        float r0, r1;
        upk2(ACCA, r0, r1); float acc0 = r0 + r1;
        upk2(ACCB, r0, r1); float acc1 = r0 + r1;

        if (n & 1) {                 // odd tail: point n-1 (slot 0 of its pair)
            int p = n - 1;
            const float* sb = s + (p >> 1) * 12;
            float x0 = sb[0], x1 = sb[2], x2 = sb[4], x3 = sb[6];
            float hA = fmaf(wa0, x0, fmaf(wa1, x1, fmaf(wa2, x2, fmaf(wa3, x3, ba))));
            float hB = fmaf(wb0, x0, fmaf(wb1, x1, fmaf(wb2, x2, fmaf(wb3, x3, bb))));
            acc0 += fmaxf(hA, 0.f);
            acc1 += fmaxf(hB, 0.f);
        }

        float inv = 1.f / fmaxf((float)n, 1.f);
        out[(size_t)m * COUT + l]      = acc0 * inv;
        out[(size_t)m * COUT + 32 + l] = acc1 * inv;
    }
}

// ---------------------------------------------------------------------------
extern "C" void kernel_launch(void* const* d_in, const int* in_sizes, int n_in,
                              void* d_out, int out_size)
{
    const float* feat  = (const float*)d_in[0];
    const int*   npts  = (const int*)d_in[1];
    const float* W     = (const float*)d_in[2];
    const float* b     = (const float*)d_in[3];
    const float* gamma = (const float*)d_in[4];
    const float* beta  = (const float*)d_in[5];
    float* out = (float*)d_out;
    int M = in_sizes[1];

    int vpb = (M + GRID - 1) / GRID;        // 136 for M=40000
    if (vpb > VPBMAX) vpb = VPBMAX;          // (problem shape fixed; stays in range)
    size_t dynbytes = (size_t)vpb * SLABW * sizeof(float);   // ~104 KB

    static int attr_done = 0;                // idempotent attribute set (host-side)
    if (!attr_done) {
        cudaFuncSetAttribute(fused_kernel,
                             cudaFuncAttributeMaxDynamicSharedMemorySize,
                             VPBMAX * SLABW * (int)sizeof(float));
        attr_done = 1;
    }

    fused_kernel<<<GRID, NTHR, dynbytes>>>(feat, npts, W, b, gamma, beta, out, M, vpb);
}